// round 10
// baseline (speedup 1.0000x reference)
#include <cuda_runtime.h>

// OpponentModelOracle: B=4096 batches, H=W=64, C=8.
// R9: two CTAs per batch (grid=8192, 256 thr, KIT=8, occ 8). Same threads/SM
// and per-thread MLP as the best configs, but per-CTA data halves at equal
// concurrency -> end-of-grid tail quantum halves (13.6us -> 6.8us).
// Cross-CTA combine via ticket: each half writes a 272B partial (food mask +
// counts + first-opp) to L2-resident scratch; the second arriver merges,
// runs the distance argmin from mask bits (no x re-read), writes the batch.

#define HW    4096
#define WDIM  64
#define NTHR  256
#define KIT   8     // cells per thread (half-batch 2048 = 256*8)
#define NWARP 8
#define NBATCH 4096
#define NGRID  8192

__device__ unsigned g_mask[NGRID][64];   // per half-batch food bitmask (2 MB)
__device__ int      g_meta[NGRID][4];    // n_food, n_opp, firstopp, pad
__device__ int      g_cnt[NBATCH];       // ticket; zero-init, reset each run

__global__ void __launch_bounds__(NTHR, 8)
oracle_kernel(const float4* __restrict__ x4,
              const float*  __restrict__ opp_start,
              float*        __restrict__ out)
{
    __shared__ unsigned s_maskfull[HW / 32];           // 128 words, whole batch
    __shared__ int s_food[NWARP], s_opp[NWARP], s_first[NWARP];
    __shared__ int s_k1[NWARP], s_v2[NWARP];
    __shared__ int s_second;
    __shared__ int s_pmeta[3];

    const int t    = threadIdx.x;
    const int warp = t >> 5;
    const int lane = t & 31;
    const int g    = blockIdx.x;
    const int b    = g >> 1;
    const int h    = g & 1;          // which half of the batch
    const int pg   = g ^ 1;          // partner CTA id

    const float4* xb = x4 + (long long)b * (HW * 2);   // 2 float4 per cell

    // ---------------- Phase 1: own half -> mask + counts + first opp -------
    int cf = 0, co = 0, fo = 0x7FFFFFFF;

    #pragma unroll
    for (int k = 0; k < KIT; k++) {
        const int cell = (h << 11) + t + (k << 8);     // 32 consecutive per warp
        float4 v = __ldcs(&xb[(long long)cell * 2]);   // streaming: ch 0..3
        const int food = (v.y == 1.0f);
        const int opp  = (v.w == 1.0f);
        const unsigned bf = __ballot_sync(0xFFFFFFFFu, food);
        const unsigned bo = __ballot_sync(0xFFFFFFFFu, opp);
        cf += __popc(bf);
        co += __popc(bo);
        if (bo) {
            const int c0 = (h << 11) + (warp << 5) + (k << 8) + (__ffs(bo) - 1);
            if (c0 < fo) fo = c0;
        }
        if (lane == k) s_maskfull[(h << 6) + warp + (k << 3)] = bf;
    }
    if (lane == 0) { s_food[warp] = cf; s_opp[warp] = co; s_first[warp] = fo; }
    __syncthreads();

    int nf_h = 0, no_h = 0, fo_h = 0x7FFFFFFF;
    #pragma unroll
    for (int i = 0; i < NWARP; i++) {
        nf_h += s_food[i];
        no_h += s_opp[i];
        if (s_first[i] < fo_h) fo_h = s_first[i];
    }

    // ---------------- Publish partial + ticket ------------------------------
    if (t < 64) g_mask[g][t] = s_maskfull[(h << 6) + t];
    if (t == 0) {
        g_meta[g][0] = nf_h;
        g_meta[g][1] = no_h;
        g_meta[g][2] = fo_h;
    }
    __threadfence();
    __syncthreads();
    if (t == 0) s_second = (atomicAdd(&g_cnt[b], 1) == 1);
    __syncthreads();
    if (!s_second) return;               // first arriver done; frees SM slot
    __threadfence();                     // acquire partner's partial

    // ---------------- Second arriver: merge partials ------------------------
    if (t < 64) s_maskfull[((1 - h) << 6) + t] = __ldcg(&g_mask[pg][t]);
    if (t == 0) {
        s_pmeta[0] = __ldcg(&g_meta[pg][0]);
        s_pmeta[1] = __ldcg(&g_meta[pg][1]);
        s_pmeta[2] = __ldcg(&g_meta[pg][2]);
    }
    __syncthreads();

    const int n_food = nf_h + s_pmeta[0];
    const int n_opp  = no_h + s_pmeta[1];
    int first = (s_pmeta[2] < fo_h) ? s_pmeta[2] : fo_h;
    if (first == 0x7FFFFFFF) first = 0;  // jnp.argmax(all-false) == 0
    const int orow = first >> 6;
    const int ocol = first & (WDIM - 1);

    // ---------------- Phase 2: two smallest distances from the mask ---------
    // key = (dsq << 12) | idx  -> lexicographic (dist, row-major idx) min,
    // matching argmin-first-occurrence. dsq <= 7938 < 2^13.
    int k1 = 0x7FFFFFFF, v2 = 0x7FFFFFFF;

    #pragma unroll
    for (int k = 0; k < 16; k++) {       // full batch: 16 cells per thread
        const int cell = t + (k << 8);
        if ((s_maskfull[cell >> 5] >> (cell & 31)) & 1) {
            const int dr = (cell >> 6) - orow;
            const int dc = (cell & (WDIM - 1)) - ocol;
            const int dsq = dr * dr + dc * dc;
            const int key = (dsq << 12) | cell;
            if (key < k1) { const int old = k1 >> 12; if (old < v2) v2 = old; k1 = key; }
            else          { if (dsq < v2) v2 = dsq; }
        }
    }
    #pragma unroll
    for (int o = 16; o; o >>= 1) {
        const int ok1 = __shfl_down_sync(0xFFFFFFFFu, k1, o);
        const int ov2 = __shfl_down_sync(0xFFFFFFFFu, v2, o);
        if (ov2 < v2) v2 = ov2;
        if (ok1 < k1) { const int old = k1 >> 12; if (old < v2) v2 = old; k1 = ok1; }
        else          { const int od  = ok1 >> 12; if (od  < v2) v2 = od; }
    }
    if (lane == 0) { s_k1[warp] = k1; s_v2[warp] = v2; }
    __syncthreads();

    k1 = 0x7FFFFFFF; v2 = 0x7FFFFFFF;
    #pragma unroll
    for (int i = 0; i < NWARP; i++) {
        const int ok1 = s_k1[i], ov2 = s_v2[i];
        if (ov2 < v2) v2 = ov2;
        if (ok1 < k1) { const int old = k1 >> 12; if (old < v2) v2 = old; k1 = ok1; }
        else          { const int od  = ok1 >> 12; if (od  < v2) v2 = od; }
    }

    // ---------------- Branch flags ------------------------------------------
    const float min1 = __fsqrt_rn((float)(k1 >> 12));
    const float min2 = __fsqrt_rn((float)v2);
    const float diff = min2 - min1;
    const int   min_idx = k1 & (HW - 1);

    const float os0 = __ldg(&opp_start[0]);
    const float os1 = __ldg(&opp_start[1]);
    const bool matches   = ((float)orow == os0) && ((float)ocol == os1);
    const bool branchA   = (n_food > 1) && (n_opp > 0) && !matches;
    const bool ambiguous = (branchA && (diff < 0.1f)) || ((n_food > 1) && !branchA);
    const bool pick      = (branchA && (diff >= 0.1f)) || (n_food == 1);

    // ---------------- Phase 3: write whole batch (4x STG.128.CS) ------------
    // Thread t owns floats [16t, 16t+16): mask bits = 16-bit slice of word t>>1.
    {
        const unsigned m16 = (s_maskfull[t >> 1] >> ((t & 1) << 4)) & 0xFFFFu;
        const int base = t << 4;
        float4* ob4 = (float4*)(out + (long long)b * HW + base);
        #pragma unroll
        for (int q = 0; q < 4; q++) {
            float r[4];
            #pragma unroll
            for (int j = 0; j < 4; j++) {
                const int c = base + (q << 2) + j;
                int hit;
                if (ambiguous)      hit = (m16 >> ((q << 2) + j)) & 1;
                else if (pick)      hit = (c == min_idx);
                else                hit = 0;
                r[j] = hit ? 10.0f : -10.0f;
            }
            __stcs(&ob4[q], make_float4(r[0], r[1], r[2], r[3]));
        }
    }

    __syncthreads();
    if (t == 0) g_cnt[b] = 0;            // leave ticket clean for next replay
}

extern "C" void kernel_launch(void* const* d_in, const int* in_sizes, int n_in,
                              void* d_out, int out_size)
{
    // metadata order: x [B,H,W,C] f32, opp_start [2] f32 — disambiguate by size.
    int xi = 0, si = 1;
    if (n_in >= 2 && in_sizes[0] <= 2) { xi = 1; si = 0; }
    const float4* x   = (const float4*)d_in[xi];
    const float*  ops = (const float*)d_in[si];
    float* out = (float*)d_out;

    oracle_kernel<<<NGRID, NTHR>>>(x, ops, out);
}

// round 12
// speedup vs baseline: 1.0583x; 1.0583x over previous
#include <cuda_runtime.h>

// OpponentModelOracle: B=4096 batches, H=W=64, C=8.
// R10 = R7 (best: 92.35us bench / 88.35us ncu) with phase-1 reductions done
// via ballot/popc instead of per-thread adds + 3-value shuffle tree.
// One CTA per batch (grid=4096, dynamic scheduling). 512 threads/CTA, occ 4,
// KIT=8 (per-thread MLP=8 — proven shape). Streaming hints on both streams.
// Warp w's lanes cover 32 consecutive cells per k-iter, so ballot gives the
// warp's food/opp masks directly: counts = popc, first-opp = ffs. The whole
// shuffle reduction and the dependent firstopp compare chain disappear.

#define HW    4096
#define WDIM  64
#define NTHR  512
#define KIT   8     // HW / NTHR
#define NWARP 16

__global__ void __launch_bounds__(NTHR, 4)
oracle_kernel(const float4* __restrict__ x4,
              const float*  __restrict__ opp_start,
              float*        __restrict__ out)
{
    __shared__ int s_food[NWARP], s_opp[NWARP], s_first[NWARP];
    __shared__ int s_k1[NWARP], s_v2[NWARP];

    const int t    = threadIdx.x;
    const int warp = t >> 5;
    const int lane = t & 31;
    const long long b = blockIdx.x;

    const float4* xb = x4 + b * (long long)(HW * 2);   // 2 float4 per cell

    // ---------------- Phase 1: masks + counts + first opponent -------------
    // cell = warp*32 + k*512 + lane -> warp's 32 lanes are consecutive cells.
    int foodbits = 0;            // bit k: this thread's cell k is food
    int cf = 0, co = 0;          // warp totals (lane-invariant via ballot)
    int fo = 0x7FFFFFFF;         // warp's first opp cell (lane-invariant)

    #pragma unroll
    for (int k = 0; k < KIT; k++) {
        const int cell = t + (k << 9);
        float4 v = __ldcs(&xb[(long long)cell * 2]);   // streaming: ch 0..3
        const int food = (v.y == 1.0f);
        const int opp  = (v.w == 1.0f);
        foodbits |= food << k;
        const unsigned bf = __ballot_sync(0xFFFFFFFFu, food);
        const unsigned bo = __ballot_sync(0xFFFFFFFFu, opp);
        cf += __popc(bf);
        co += __popc(bo);
        if (bo) {
            const int c0 = (warp << 5) + (k << 9) + (__ffs(bo) - 1);
            if (c0 < fo) fo = c0;
        }
    }
    if (lane == 0) { s_food[warp] = cf; s_opp[warp] = co; s_first[warp] = fo; }
    __syncthreads();

    int n_food = 0, n_opp = 0, first = 0x7FFFFFFF;
    #pragma unroll
    for (int i = 0; i < NWARP; i++) {
        n_food += s_food[i];
        n_opp  += s_opp[i];
        if (s_first[i] < first) first = s_first[i];
    }
    if (first == 0x7FFFFFFF) first = 0;   // jnp.argmax(all-false) == 0
    const int orow = first >> 6;
    const int ocol = first & (WDIM - 1);

    // ---------------- Phase 2: two smallest distances over food cells ------
    // key = (dsq << 12) | idx  -> lexicographic (distance, row-major idx) min,
    // matching argmin-first-occurrence semantics. dsq <= 7938 < 2^13.
    int k1 = 0x7FFFFFFF;   // packed best
    int v2 = 0x7FFFFFFF;   // second-best dsq (min over all but argmin element)

    #pragma unroll
    for (int k = 0; k < KIT; k++) {
        if ((foodbits >> k) & 1) {
            const int cell = t + (k << 9);
            const int dr = (cell >> 6) - orow;
            const int dc = (cell & (WDIM - 1)) - ocol;
            const int dsq = dr * dr + dc * dc;
            const int key = (dsq << 12) | cell;
            if (key < k1) { const int old = k1 >> 12; if (old < v2) v2 = old; k1 = key; }
            else          { if (dsq < v2) v2 = dsq; }
        }
    }
    #pragma unroll
    for (int o = 16; o; o >>= 1) {
        const int ok1 = __shfl_down_sync(0xFFFFFFFFu, k1, o);
        const int ov2 = __shfl_down_sync(0xFFFFFFFFu, v2, o);
        if (ov2 < v2) v2 = ov2;
        if (ok1 < k1) { const int old = k1 >> 12; if (old < v2) v2 = old; k1 = ok1; }
        else          { const int od  = ok1 >> 12; if (od  < v2) v2 = od; }
    }
    if (lane == 0) { s_k1[warp] = k1; s_v2[warp] = v2; }
    __syncthreads();

    k1 = 0x7FFFFFFF; v2 = 0x7FFFFFFF;
    #pragma unroll
    for (int i = 0; i < NWARP; i++) {
        const int ok1 = s_k1[i], ov2 = s_v2[i];
        if (ov2 < v2) v2 = ov2;
        if (ok1 < k1) { const int old = k1 >> 12; if (old < v2) v2 = old; k1 = ok1; }
        else          { const int od  = ok1 >> 12; if (od  < v2) v2 = od; }
    }

    // ---------------- Branch flags (computed redundantly by all threads) ---
    const float min1 = __fsqrt_rn((float)(k1 >> 12));
    const float min2 = __fsqrt_rn((float)v2);
    const float diff = min2 - min1;
    const int   min_idx = k1 & (HW - 1);

    const float os0 = __ldg(&opp_start[0]);
    const float os1 = __ldg(&opp_start[1]);
    const bool matches   = ((float)orow == os0) && ((float)ocol == os1);
    const bool branchA   = (n_food > 1) && (n_opp > 0) && !matches;
    const bool ambiguous = (branchA && (diff < 0.1f)) || ((n_food > 1) && !branchA);
    const bool pick      = (branchA && (diff >= 0.1f)) || (n_food == 1);

    // ---------------- Phase 3: streaming coalesced write -------------------
    float* ob = out + b * (long long)HW;
    #pragma unroll
    for (int k = 0; k < KIT; k++) {
        const int cell = t + (k << 9);
        const int food = (foodbits >> k) & 1;
        int hit;
        if (ambiguous)      hit = food;
        else if (pick)      hit = (cell == min_idx);
        else                hit = 0;
        __stcs(&ob[cell], hit ? 10.0f : -10.0f);
    }
}

extern "C" void kernel_launch(void* const* d_in, const int* in_sizes, int n_in,
                              void* d_out, int out_size)
{
    // metadata order: x [B,H,W,C] f32, opp_start [2] f32 — disambiguate by size.
    int xi = 0, si = 1;
    if (n_in >= 2 && in_sizes[0] <= 2) { xi = 1; si = 0; }
    const float4* x   = (const float4*)d_in[xi];
    const float*  ops = (const float*)d_in[si];
    float* out = (float*)d_out;

    oracle_kernel<<<4096, NTHR>>>(x, ops, out);
}